// round 9
// baseline (speedup 1.0000x reference)
#include <cuda_runtime.h>
#include <math.h>

// A=16, NA=8, D_OBS=64, DZ=72, Bn=128.
// Output: value[262144] | weight_z[32768] | weights_obsz[524288]

#define NTHREADS 256

// ---------------- cross-launch intermediates ----------------
__device__ float g_w   [32768];
__device__ float g_wo  [32768];
__device__ float g_u_av[2048*64];
__device__ float g_v_av[2048*64];
__device__ float g_U   [2048*64];
__device__ float g_FmP [2048*64];
__device__ float g_Ct  [64*65];
__device__ float g_fb  [64];

__device__ __forceinline__ float leaky(float x){ return x > 0.f ? x : 0.01f*x; }

__device__ __forceinline__ void load_wT(const float* __restrict__ w, int in_n, float* wt){
    for (int idx = threadIdx.x; idx < 64*in_n; idx += NTHREADS) {
        int t = idx / in_n, c = idx - t*in_n;
        wt[c*65 + t] = w[idx];
    }
}

// Dual-weight GEMM: one input, two weight sets. 16 rows x 64 outs, 256 threads.
template<int CIN, int LDIN, bool LKA, bool LKB>
__device__ __forceinline__ void g16_2w(const float* __restrict__ in_s,
                                       const float* __restrict__ wA, const float* __restrict__ bA,
                                       float* __restrict__ oA,
                                       const float* __restrict__ wB, const float* __restrict__ bB,
                                       float* __restrict__ oB)
{
    int t  = threadIdx.x & 63;
    int rg = threadIdx.x >> 6;
    float accA[4], accB[4];
    float biasA = bA ? bA[t] : 0.f, biasB = bB ? bB[t] : 0.f;
    #pragma unroll
    for (int k = 0; k < 4; k++){ accA[k] = biasA; accB[k] = biasB; }
    #pragma unroll
    for (int c4 = 0; c4 < CIN/4; c4++) {
        float a0 = wA[(c4*4+0)*65 + t], a1 = wA[(c4*4+1)*65 + t];
        float a2 = wA[(c4*4+2)*65 + t], a3 = wA[(c4*4+3)*65 + t];
        float b0 = wB[(c4*4+0)*65 + t], b1 = wB[(c4*4+1)*65 + t];
        float b2 = wB[(c4*4+2)*65 + t], b3 = wB[(c4*4+3)*65 + t];
        #pragma unroll
        for (int k = 0; k < 4; k++) {
            float4 v = *reinterpret_cast<const float4*>(&in_s[(rg*4+k)*LDIN + c4*4]);
            accA[k] = fmaf(v.x,a0, fmaf(v.y,a1, fmaf(v.z,a2, fmaf(v.w,a3, accA[k]))));
            accB[k] = fmaf(v.x,b0, fmaf(v.y,b1, fmaf(v.z,b2, fmaf(v.w,b3, accB[k]))));
        }
    }
    #pragma unroll
    for (int k = 0; k < 4; k++) {
        oA[(rg*4+k)*64 + t] = LKA ? leaky(accA[k]) : accA[k];
        oB[(rg*4+k)*64 + t] = LKB ? leaky(accB[k]) : accB[k];
    }
}

// Dual-io GEMM: two inputs, two weight sets. 16 rows x 64 outs.
template<int CIN, bool LKA, bool LKB>
__device__ __forceinline__ void g16_2io(const float* __restrict__ inA,
                                        const float* __restrict__ wA, const float* __restrict__ bA,
                                        float* __restrict__ oA,
                                        const float* __restrict__ inB,
                                        const float* __restrict__ wB, const float* __restrict__ bB,
                                        float* __restrict__ oB)
{
    int t  = threadIdx.x & 63;
    int rg = threadIdx.x >> 6;
    float accA[4], accB[4];
    float biasA = bA ? bA[t] : 0.f, biasB = bB ? bB[t] : 0.f;
    #pragma unroll
    for (int k = 0; k < 4; k++){ accA[k] = biasA; accB[k] = biasB; }
    #pragma unroll
    for (int c4 = 0; c4 < CIN/4; c4++) {
        float a0 = wA[(c4*4+0)*65 + t], a1 = wA[(c4*4+1)*65 + t];
        float a2 = wA[(c4*4+2)*65 + t], a3 = wA[(c4*4+3)*65 + t];
        float b0 = wB[(c4*4+0)*65 + t], b1 = wB[(c4*4+1)*65 + t];
        float b2 = wB[(c4*4+2)*65 + t], b3 = wB[(c4*4+3)*65 + t];
        #pragma unroll
        for (int k = 0; k < 4; k++) {
            float4 va = *reinterpret_cast<const float4*>(&inA[(rg*4+k)*64 + c4*4]);
            float4 vb = *reinterpret_cast<const float4*>(&inB[(rg*4+k)*64 + c4*4]);
            accA[k] = fmaf(va.x,a0, fmaf(va.y,a1, fmaf(va.z,a2, fmaf(va.w,a3, accA[k]))));
            accB[k] = fmaf(vb.x,b0, fmaf(vb.y,b1, fmaf(vb.z,b2, fmaf(vb.w,b3, accB[k]))));
        }
    }
    #pragma unroll
    for (int k = 0; k < 4; k++) {
        oA[(rg*4+k)*64 + t] = LKA ? leaky(accA[k]) : accA[k];
        oB[(rg*4+k)*64 + t] = LKB ? leaky(accB[k]) : accB[k];
    }
}

// 32 rows x 64 outs (L2 G-build)
__device__ __forceinline__ void gemm32(const float* __restrict__ in_s,
                                       const float* __restrict__ wT,
                                       float* __restrict__ out, int ldout)
{
    int t  = threadIdx.x & 63;
    int rg = threadIdx.x >> 6;
    float acc[8];
    #pragma unroll
    for (int k = 0; k < 8; k++) acc[k] = 0.f;
    #pragma unroll
    for (int c4 = 0; c4 < 16; c4++) {
        float w0 = wT[(c4*4+0)*65 + t];
        float w1 = wT[(c4*4+1)*65 + t];
        float w2 = wT[(c4*4+2)*65 + t];
        float w3 = wT[(c4*4+3)*65 + t];
        #pragma unroll
        for (int k = 0; k < 8; k++) {
            float4 v = *reinterpret_cast<const float4*>(&in_s[(rg*8+k)*64 + c4*4]);
            acc[k] = fmaf(v.x, w0, fmaf(v.y, w1, fmaf(v.z, w2, fmaf(v.w, w3, acc[k]))));
        }
    }
    #pragma unroll
    for (int k = 0; k < 8; k++) out[(rg*8+k)*ldout + t] = acc[k];
}

// ================= L1: one block per batch; block 128 = kF0 =================
__global__ void L1(const float* __restrict__ obs, const float* __restrict__ pol,
                   const float* __restrict__ act,
                   const float* kw1, const float* kb1, const float* kw2, const float* kb2,
                   const float* qw1, const float* qb1, const float* qw2, const float* qb2,
                   const float* ko1, const float* ko1b, const float* ko2, const float* ko2b,
                   const float* qo1, const float* qo1b, const float* qo2, const float* qo2b,
                   const float* av1, const float* av1b, const float* av2w, const float* av2b,
                   const float* fv1, const float* fv1b,
                   float* __restrict__ out_wz)
{
    extern __shared__ float sm[];
    int bx = blockIdx.x;
    int tid = threadIdx.x;

    if (bx == 128) {   // ---- kF0 ----
        float* fm  = sm;           // 4096
        float* w2t = sm + 4096;    // 4160
        float* b2  = sm + 8256;    // 64
        for (int idx = tid; idx < 4096; idx += NTHREADS) {
            int t = idx >> 6, c = idx & 63;
            fm[idx] = fv1[t*128 + 64 + c];
            w2t[(idx & 63)*65 + (idx >> 6)] = av2w[idx];
        }
        if (tid < 64) b2[tid] = av2b[tid];
        __syncthreads();
        for (int idx = tid; idx < 4096; idx += NTHREADS) {
            int t = idx & 63, e = idx >> 6;
            float s = 0.f;
            for (int c = 0; c < 64; c++) {
                int cc = (c + t) & 63;
                s = fmaf(fm[t*64 + cc], w2t[e*65 + cc], s);
            }
            g_Ct[e*65 + t] = s;
        }
        if (tid < 64) {
            float s = 0.f;
            for (int c = 0; c < 64; c++) {
                int cc = (c + tid) & 63;
                s = fmaf(fm[tid*64 + cc], b2[cc], s);
            }
            g_fb[tid] = s;
        }
        return;
    }

    int b = bx;
    float* wA    = sm;             // 4680
    float* wB    = sm + 4680;      // 4680
    float* obs16 = sm + 9360;      // 1024
    float* pol16 = sm + 10384;     // 128
    float* dl    = sm + 10512;     // 128
    float* src   = sm + 10640;     // 1152
    float* op    = sm + 11792;     // 1152
    float* hA    = sm + 12944;     // 1024
    float* hB    = sm + 13968;     // 1024
    float* kz    = sm + 14992;     // 1024  (reused as hC after S3)
    float* qz    = sm + 16016;     // 1024
    float* keyo  = sm + 17040;     // 1024
    float* atts  = sm + 18064;     // 1024
    float* uqo   = sm + 19088;     // 1024
    float* uav   = sm + 20112;     // 1024
    float* vqo   = sm + 21136;     // 1024
    float* vav   = sm + 22160;     // 1024
    float* kq    = sm + 23184;     // 1024
    float* Ps    = sm + 24208;     // 1024
    float* w_sm  = sm + 25232;     // 256
    float* kb_s  = sm + 25488;     // 16
    float* hC    = kz;

    int i = tid >> 4, j = tid & 15;

    for (int idx = tid; idx < 1024; idx += NTHREADS) obs16[idx] = obs[(size_t)b*1024 + idx];
    if (tid < 128) {
        float p = pol[b*128 + tid];
        pol16[tid] = p;
        dl[tid]    = act[b*128 + tid] - p;
    }
    // S1: hA = leaky(kw1.obs), hB = leaky(qw1.obs)
    load_wT(kw1, 64, wA); load_wT(qw1, 64, wB);
    __syncthreads();
    g16_2w<64,64,true,true>(obs16, wA, kb1, hA, wB, qb1, hB);
    __syncthreads();
    // S2: kz = kw2.hA, qz = qw2.hB
    load_wT(kw2, 64, wA); load_wT(qw2, 64, wB);
    __syncthreads();
    g16_2io<64,false,false>(hA, wA, kb2, kz, hB, wB, qb2, qz);
    __syncthreads();
    // S3: w = sigmoid(qz.kz / 8)
    {
        float acc = 0.f;
        #pragma unroll
        for (int d = 0; d < 64; d++) {
            int dd = (d + 2*j) & 63;
            acc = fmaf(qz[i*64 + dd], kz[j*64 + dd], acc);
        }
        float w = 1.f / (1.f + expf(-acc * 0.125f));
        w_sm[tid] = w;
        g_w[b*256 + tid] = w;
        out_wz[b*256 + tid] = w;
    }
    __syncthreads();
    // S4: src/op rows
    for (int idx = tid; idx < 1152; idx += NTHREADS) {
        int r = idx / 72, c = idx - r*72;
        float vs, vo;
        if (c < 64) { float o = obs16[r*64 + c]; vs = o; vo = o; }
        else {
            int n = c - 64;
            float p = pol16[r*8 + n];
            vs = fmaf(w_sm[r*17], dl[r*8 + n], p);
            vo = p;
        }
        src[idx] = vs; op[idx] = vo;
    }
    // S5: hA = leaky(ko1.src), hB = leaky(av1.src)
    load_wT(ko1, 72, wA); load_wT(av1, 72, wB);
    __syncthreads();
    g16_2w<72,72,true,true>(src, wA, ko1b, hA, wB, av1b, hB);
    __syncthreads();
    // S6: load wA=qo1, KEEP wB=av1. uqo/uav (pre-act), then vqo/vav, hC=leaky(uav)
    load_wT(qo1, 72, wA);
    __syncthreads();
    g16_2w<72,72,false,false>(op, wA, qo1b, uqo, wB, av1b, uav);
    g16_2w<8,8,false,false>(dl, wA + 64*65, nullptr, vqo, wB + 64*65, nullptr, vav);
    __syncthreads();
    for (int idx = tid; idx < 1024; idx += NTHREADS) {
        hC[idx] = leaky(uav[idx]);
        g_u_av[b*1024 + idx] = uav[idx];
        g_v_av[b*1024 + idx] = vav[idx];
    }
    // S7: keyo = ko2.hA, atts = av2.hB
    load_wT(ko2, 64, wA); load_wT(av2w, 64, wB);
    __syncthreads();
    g16_2io<64,false,false>(hA, wA, ko2b, keyo, hB, wB, av2b, atts);
    __syncthreads();
    // S8: load wA=qo2, KEEP wB=av2w. kq = keyo@W2qo ; Ps = av2.hC + av2b
    for (int idx = tid; idx < 4096; idx += NTHREADS) {
        int c = idx >> 6, t = idx & 63;
        wA[c*65 + t] = qo2[idx];
    }
    __syncthreads();
    g16_2io<64,false,false>(keyo, wA, nullptr, kq, hC, wB, av2b, Ps);
    if (tid < 16) {
        float s = 0.f;
        for (int c = 0; c < 64; c++) {
            int cc = (c + 4*tid) & 63;
            s = fmaf(keyo[tid*64 + cc], qo2b[cc], s);
        }
        kb_s[tid] = s;
    }
    __syncthreads();
    // S9: U = atts@fv1a^T + fv1b ; FmP = Ps@Fm^T   (to global)
    for (int idx = tid; idx < 4096; idx += NTHREADS) {
        int t = idx >> 6, c = idx & 63;
        wA[c*65 + t] = fv1[t*128 + c];
        wB[c*65 + t] = fv1[t*128 + 64 + c];
    }
    __syncthreads();
    g16_2io<64,false,false>(atts, wA, fv1b, g_U + b*1024, Ps, wB, nullptr, g_FmP + b*1024);
    // S10: wo softmax
    {
        float wv = w_sm[tid];
        float acc = kb_s[i];
        #pragma unroll
        for (int d = 0; d < 64; d++) {
            int dd = (d + 2*j) & 63;
            float h = leaky(fmaf(wv, vqo[j*64 + dd], uqo[j*64 + dd]));
            acc = fmaf(kq[i*64 + dd], h, acc);
        }
        float sc = fminf(fmaxf(acc * 0.125f, -5.f), 5.f);
        float t = expf(sc);
        float mx = t;
        #pragma unroll
        for (int m = 1; m < 16; m <<= 1) mx = fmaxf(mx, __shfl_xor_sync(0xffffffffu, mx, m));
        float e = expf(t - mx), s = e;
        #pragma unroll
        for (int m = 1; m < 16; m <<= 1) s += __shfl_xor_sync(0xffffffffu, s, m);
        g_wo[b*256 + tid] = e / s;
    }
}

// ================= L2: 4 blocks per batch (i-quarters) =================
__global__ void L2(const float* __restrict__ fv2, const float* __restrict__ fv2b,
                   float* __restrict__ out_val, float4* __restrict__ out4)
{
    extern __shared__ float sm[];
    float* Ct_s  = sm;             // 4160
    float* L_s   = sm + 4160;      // 4096
    float* G_s   = sm + 8256;      // 4160
    float* u_s   = sm + 12416;     // 1024
    float* v_s   = sm + 13440;     // 1024
    float* U_s   = sm + 14464;     // 1040
    float* Fp_s  = sm + 15504;     // 1040
    float* w_s   = sm + 16544;     // 64
    float* wo_s  = sm + 16608;     // 256
    float* fb_s  = sm + 16864;     // 64
    float* fv2_s = sm + 16928;     // 512
    float* b2v   = sm + 17440;     // 8
    // 17448 floats = 69792 B -> 3 blocks/SM

    int bx = blockIdx.x;
    int b  = bx >> 2, iq = bx & 3;
    int tid = threadIdx.x;

    for (int idx = tid; idx < 4160; idx += NTHREADS) Ct_s[idx] = g_Ct[idx];
    for (int idx = tid; idx < 1024; idx += NTHREADS) {
        u_s[idx] = g_u_av[b*1024 + idx];
        v_s[idx] = g_v_av[b*1024 + idx];
        int r = idx >> 6, c = idx & 63;
        U_s [r*65 + c] = g_U  [b*1024 + idx];
        Fp_s[r*65 + c] = g_FmP[b*1024 + idx];
    }
    if (tid < 64)  w_s[tid] = g_w[b*256 + iq*64 + tid];
    wo_s[tid] = g_wo[b*256 + tid];
    if (tid < 64)  fb_s[tid] = g_fb[tid];
    for (int idx = tid; idx < 512; idx += NTHREADS) fv2_s[idx] = fv2[idx];
    if (tid < 8)   b2v[tid] = fv2b[tid];
    __syncthreads();
    // L rows [iq*64, iq*64+64): L[r][t] = leaky(u[j] + w*v[j]), j = r & 15
    for (int idx = tid; idx < 4096; idx += NTHREADS) {
        int r = idx >> 6, t = idx & 63;
        int j = r & 15;
        L_s[idx] = leaky(fmaf(w_s[r], v_s[j*64 + t], u_s[j*64 + t]));
    }
    __syncthreads();
    gemm32(L_s,        Ct_s, G_s,         65);
    gemm32(L_s + 2048, Ct_s, G_s + 32*65, 65);
    __syncthreads();
    // value head: pair p = tid>>2 (il = p>>4, j = p&15), t-quarter q = tid&3
    int p = tid >> 2, q = tid & 3;
    int il = p >> 4, j = p & 15;
    float wo_r[16];
    #pragma unroll
    for (int k = 0; k < 16; k++) wo_r[k] = wo_s[j*16 + k];
    float wjj = wo_r[j];
    float vout[8];
    #pragma unroll
    for (int o = 0; o < 8; o++) vout[o] = 0.f;
    #pragma unroll
    for (int tt = 0; tt < 16; tt++) {
        int t = q*16 + tt;
        float m = 0.f;
        #pragma unroll
        for (int k = 0; k < 16; k++) m = fmaf(wo_r[k], G_s[(il*16 + k)*65 + t], m);
        float gij = G_s[(il*16 + j)*65 + t];
        float fbt = fb_s[t];
        float h = U_s[j*65 + t] + 0.0625f * (m + fbt + wjj * (Fp_s[j*65 + t] - gij - fbt));
        float ht = leaky(h);
        #pragma unroll
        for (int o = 0; o < 8; o++) vout[o] = fmaf(fv2_s[o*64 + t], ht, vout[o]);
    }
    #pragma unroll
    for (int o = 0; o < 8; o++) {
        vout[o] += __shfl_xor_sync(0xffffffffu, vout[o], 1);
        vout[o] += __shfl_xor_sync(0xffffffffu, vout[o], 2);
    }
    if (q == 0) {
        #pragma unroll
        for (int o = 0; o < 8; o++) vout[o] += b2v[o];
        float4* dst = reinterpret_cast<float4*>(
            out_val + (size_t)(b*256 + (iq*4 + il)*16 + j)*8);
        dst[0] = make_float4(vout[0], vout[1], vout[2], vout[3]);
        dst[1] = make_float4(vout[4], vout[5], vout[6], vout[7]);
    }
    // weights_obsz quarter: one float4 per thread
    {
        const float4* wo4 = reinterpret_cast<const float4*>(wo_s);
        int q4 = iq*256 + tid;
        out4[b*1024 + q4] = wo4[q4 & 63];
    }
}

// ---------------- launcher ----------------
extern "C" void kernel_launch(void* const* d_in, const int* in_sizes, int n_in,
                              void* d_out, int out_size)
{
    const float* obs  = (const float*)d_in[0];
    const float* pol  = (const float*)d_in[1];
    const float* act  = (const float*)d_in[2];
    const float* kw1  = (const float*)d_in[3];  const float* kw1b = (const float*)d_in[4];
    const float* kw2  = (const float*)d_in[5];  const float* kw2b = (const float*)d_in[6];
    const float* qw1  = (const float*)d_in[7];  const float* qw1b = (const float*)d_in[8];
    const float* qw2  = (const float*)d_in[9];  const float* qw2b = (const float*)d_in[10];
    const float* ko1  = (const float*)d_in[11]; const float* ko1b = (const float*)d_in[12];
    const float* ko2  = (const float*)d_in[13]; const float* ko2b = (const float*)d_in[14];
    const float* qo1  = (const float*)d_in[15]; const float* qo1b = (const float*)d_in[16];
    const float* qo2  = (const float*)d_in[17]; const float* qo2b = (const float*)d_in[18];
    const float* av1  = (const float*)d_in[19]; const float* av1b = (const float*)d_in[20];
    const float* av2  = (const float*)d_in[21]; const float* av2b = (const float*)d_in[22];
    const float* fv1  = (const float*)d_in[23]; const float* fv1b = (const float*)d_in[24];
    const float* fv2  = (const float*)d_in[25]; const float* fv2b = (const float*)d_in[26];

    float* out      = (float*)d_out;
    float* out_val  = out;
    float* out_wz   = out + 262144;
    float* out_obsz = out + 294912;

    const int SM1 = 25504 * 4;   // 102016
    const int SM2 = 17448 * 4;   // 69792

    cudaFuncSetAttribute(L1, cudaFuncAttributeMaxDynamicSharedMemorySize, SM1);
    cudaFuncSetAttribute(L2, cudaFuncAttributeMaxDynamicSharedMemorySize, SM2);

    L1<<<129, NTHREADS, SM1>>>(obs, pol, act,
                               kw1, kw1b, kw2, kw2b, qw1, qw1b, qw2, qw2b,
                               ko1, ko1b, ko2, ko2b, qo1, qo1b, qo2, qo2b,
                               av1, av1b, av2, av2b, fv1, fv1b, out_wz);
    L2<<<512, NTHREADS, SM2>>>(fv2, fv2b, out_val,
                               reinterpret_cast<float4*>(out_obsz));
}

// round 10
// speedup vs baseline: 1.6774x; 1.6774x over previous
#include <cuda_runtime.h>
#include <math.h>

// A=16, NA=8, D_OBS=64, DZ=72, Bn=128.
// Output: value[262144] | weight_z[32768] | weights_obsz[524288]

#define NT1 512
#define NT2 256

// ---------------- cross-launch intermediates ----------------
__device__ float g_w   [32768];
__device__ float g_wo  [32768];
__device__ float g_u_av[2048*64];
__device__ float g_v_av[2048*64];
__device__ float g_U   [2048*64];
__device__ float g_FmP [2048*64];
__device__ float g_Ct  [64*65];
__device__ float g_fb  [64];

__device__ __forceinline__ float leaky(float x){ return x > 0.f ? x : 0.01f*x; }

__device__ __forceinline__ void load_wT(const float* __restrict__ w, int in_n, float* wt){
    for (int idx = threadIdx.x; idx < 64*in_n; idx += blockDim.x) {
        int t = idx / in_n, c = idx - t*in_n;
        wt[c*65 + t] = w[idx];
    }
}

// Dual-weight GEMM: one input, two weight sets. 16 rows x 64 outs, NT threads.
template<int NT, int CIN, int LDIN, bool LKA, bool LKB>
__device__ __forceinline__ void g16_2w(const float* __restrict__ in_s,
                                       const float* __restrict__ wA, const float* __restrict__ bA,
                                       float* __restrict__ oA,
                                       const float* __restrict__ wB, const float* __restrict__ bB,
                                       float* __restrict__ oB)
{
    constexpr int RPG = 16 / (NT/64);   // rows per group
    int t  = threadIdx.x & 63;
    int rg = threadIdx.x >> 6;
    float accA[RPG], accB[RPG];
    float biasA = bA ? bA[t] : 0.f, biasB = bB ? bB[t] : 0.f;
    #pragma unroll
    for (int k = 0; k < RPG; k++){ accA[k] = biasA; accB[k] = biasB; }
    #pragma unroll
    for (int c4 = 0; c4 < CIN/4; c4++) {
        float a0 = wA[(c4*4+0)*65 + t], a1 = wA[(c4*4+1)*65 + t];
        float a2 = wA[(c4*4+2)*65 + t], a3 = wA[(c4*4+3)*65 + t];
        float b0 = wB[(c4*4+0)*65 + t], b1 = wB[(c4*4+1)*65 + t];
        float b2 = wB[(c4*4+2)*65 + t], b3 = wB[(c4*4+3)*65 + t];
        #pragma unroll
        for (int k = 0; k < RPG; k++) {
            float4 v = *reinterpret_cast<const float4*>(&in_s[(rg*RPG+k)*LDIN + c4*4]);
            accA[k] = fmaf(v.x,a0, fmaf(v.y,a1, fmaf(v.z,a2, fmaf(v.w,a3, accA[k]))));
            accB[k] = fmaf(v.x,b0, fmaf(v.y,b1, fmaf(v.z,b2, fmaf(v.w,b3, accB[k]))));
        }
    }
    #pragma unroll
    for (int k = 0; k < RPG; k++) {
        oA[(rg*RPG+k)*64 + t] = LKA ? leaky(accA[k]) : accA[k];
        oB[(rg*RPG+k)*64 + t] = LKB ? leaky(accB[k]) : accB[k];
    }
}

// Dual-io GEMM: two inputs, two weight sets. 16 rows x 64 outs.
template<int NT, int CIN, bool LKA, bool LKB>
__device__ __forceinline__ void g16_2io(const float* __restrict__ inA,
                                        const float* __restrict__ wA, const float* __restrict__ bA,
                                        float* __restrict__ oA,
                                        const float* __restrict__ inB,
                                        const float* __restrict__ wB, const float* __restrict__ bB,
                                        float* __restrict__ oB)
{
    constexpr int RPG = 16 / (NT/64);
    int t  = threadIdx.x & 63;
    int rg = threadIdx.x >> 6;
    float accA[RPG], accB[RPG];
    float biasA = bA ? bA[t] : 0.f, biasB = bB ? bB[t] : 0.f;
    #pragma unroll
    for (int k = 0; k < RPG; k++){ accA[k] = biasA; accB[k] = biasB; }
    #pragma unroll
    for (int c4 = 0; c4 < CIN/4; c4++) {
        float a0 = wA[(c4*4+0)*65 + t], a1 = wA[(c4*4+1)*65 + t];
        float a2 = wA[(c4*4+2)*65 + t], a3 = wA[(c4*4+3)*65 + t];
        float b0 = wB[(c4*4+0)*65 + t], b1 = wB[(c4*4+1)*65 + t];
        float b2 = wB[(c4*4+2)*65 + t], b3 = wB[(c4*4+3)*65 + t];
        #pragma unroll
        for (int k = 0; k < RPG; k++) {
            float4 va = *reinterpret_cast<const float4*>(&inA[(rg*RPG+k)*64 + c4*4]);
            float4 vb = *reinterpret_cast<const float4*>(&inB[(rg*RPG+k)*64 + c4*4]);
            accA[k] = fmaf(va.x,a0, fmaf(va.y,a1, fmaf(va.z,a2, fmaf(va.w,a3, accA[k]))));
            accB[k] = fmaf(vb.x,b0, fmaf(vb.y,b1, fmaf(vb.z,b2, fmaf(vb.w,b3, accB[k]))));
        }
    }
    #pragma unroll
    for (int k = 0; k < RPG; k++) {
        oA[(rg*RPG+k)*64 + t] = LKA ? leaky(accA[k]) : accA[k];
        oB[(rg*RPG+k)*64 + t] = LKB ? leaky(accB[k]) : accB[k];
    }
}

// 32 rows x 64 outs, 256 threads (L2 G-build)
__device__ __forceinline__ void gemm32(const float* __restrict__ in_s,
                                       const float* __restrict__ wT,
                                       float* __restrict__ out, int ldout)
{
    int t  = threadIdx.x & 63;
    int rg = threadIdx.x >> 6;
    float acc[8];
    #pragma unroll
    for (int k = 0; k < 8; k++) acc[k] = 0.f;
    #pragma unroll
    for (int c4 = 0; c4 < 16; c4++) {
        float w0 = wT[(c4*4+0)*65 + t];
        float w1 = wT[(c4*4+1)*65 + t];
        float w2 = wT[(c4*4+2)*65 + t];
        float w3 = wT[(c4*4+3)*65 + t];
        #pragma unroll
        for (int k = 0; k < 8; k++) {
            float4 v = *reinterpret_cast<const float4*>(&in_s[(rg*8+k)*64 + c4*4]);
            acc[k] = fmaf(v.x, w0, fmaf(v.y, w1, fmaf(v.z, w2, fmaf(v.w, w3, acc[k]))));
        }
    }
    #pragma unroll
    for (int k = 0; k < 8; k++) out[(rg*8+k)*ldout + t] = acc[k];
}

// ================= L1: one block per batch (512 thr); block 128 = kF0 =================
__global__ void __launch_bounds__(NT1, 1)
L1(const float* __restrict__ obs, const float* __restrict__ pol,
   const float* __restrict__ act,
   const float* kw1, const float* kb1, const float* kw2, const float* kb2,
   const float* qw1, const float* qb1, const float* qw2, const float* qb2,
   const float* ko1, const float* ko1b, const float* ko2, const float* ko2b,
   const float* qo1, const float* qo1b, const float* qo2, const float* qo2b,
   const float* av1, const float* av1b, const float* av2w, const float* av2b,
   const float* fv1, const float* fv1b,
   float* __restrict__ out_wz)
{
    extern __shared__ float sm[];
    int bx = blockIdx.x;
    int tid = threadIdx.x;

    if (bx == 128) {   // ---- kF0 ----
        float* fm  = sm;           // 4096
        float* w2t = sm + 4096;    // 4160
        float* b2  = sm + 8256;    // 64
        for (int idx = tid; idx < 4096; idx += NT1) {
            int t = idx >> 6, c = idx & 63;
            fm[idx] = fv1[t*128 + 64 + c];
            w2t[(idx & 63)*65 + (idx >> 6)] = av2w[idx];
        }
        if (tid < 64) b2[tid] = av2b[tid];
        __syncthreads();
        for (int idx = tid; idx < 4096; idx += NT1) {
            int t = idx & 63, e = idx >> 6;
            float s = 0.f;
            for (int c = 0; c < 64; c++) {
                int cc = (c + t) & 63;
                s = fmaf(fm[t*64 + cc], w2t[e*65 + cc], s);
            }
            g_Ct[e*65 + t] = s;
        }
        if (tid < 64) {
            float s = 0.f;
            for (int c = 0; c < 64; c++) {
                int cc = (c + tid) & 63;
                s = fmaf(fm[tid*64 + cc], b2[cc], s);
            }
            g_fb[tid] = s;
        }
        return;
    }

    int b = bx;
    float* wA    = sm;             // 4680
    float* wB    = sm + 4680;      // 4680
    float* obs16 = sm + 9360;      // 1024
    float* pol16 = sm + 10384;     // 128
    float* dl    = sm + 10512;     // 128
    float* src   = sm + 10640;     // 1152
    float* op    = sm + 11792;     // 1152
    float* hA    = sm + 12944;     // 1024
    float* hB    = sm + 13968;     // 1024
    float* kz    = sm + 14992;     // 1024  (reused as hC)
    float* qz    = sm + 16016;     // 1024
    float* keyo  = sm + 17040;     // 1024
    float* atts  = sm + 18064;     // 1024
    float* uqo   = sm + 19088;     // 1024
    float* uav   = sm + 20112;     // 1024
    float* vqo   = sm + 21136;     // 1024
    float* vav   = sm + 22160;     // 1024
    float* kq    = sm + 23184;     // 1024
    float* Ps    = sm + 24208;     // 1024
    float* w_sm  = sm + 25232;     // 256
    float* kb_s  = sm + 25488;     // 16
    float* hC    = kz;

    for (int idx = tid; idx < 1024; idx += NT1) obs16[idx] = obs[(size_t)b*1024 + idx];
    if (tid < 128) {
        float p = pol[b*128 + tid];
        pol16[tid] = p;
        dl[tid]    = act[b*128 + tid] - p;
    }
    // S1
    load_wT(kw1, 64, wA); load_wT(qw1, 64, wB);
    __syncthreads();
    g16_2w<NT1,64,64,true,true>(obs16, wA, kb1, hA, wB, qb1, hB);
    __syncthreads();
    // S2
    load_wT(kw2, 64, wA); load_wT(qw2, 64, wB);
    __syncthreads();
    g16_2io<NT1,64,false,false>(hA, wA, kb2, kz, hB, wB, qb2, qz);
    __syncthreads();
    // S3: w = sigmoid(qz.kz / 8)
    if (tid < 256) {
        int i = tid >> 4, j = tid & 15;
        float acc = 0.f;
        #pragma unroll
        for (int d = 0; d < 64; d++) {
            int dd = (d + 2*j) & 63;
            acc = fmaf(qz[i*64 + dd], kz[j*64 + dd], acc);
        }
        float w = 1.f / (1.f + expf(-acc * 0.125f));
        w_sm[tid] = w;
        g_w[b*256 + tid] = w;
        out_wz[b*256 + tid] = w;
    }
    __syncthreads();
    // S4: src/op rows
    for (int idx = tid; idx < 1152; idx += NT1) {
        int r = idx / 72, c = idx - r*72;
        float vs, vo;
        if (c < 64) { float o = obs16[r*64 + c]; vs = o; vo = o; }
        else {
            int n = c - 64;
            float p = pol16[r*8 + n];
            vs = fmaf(w_sm[r*17], dl[r*8 + n], p);
            vo = p;
        }
        src[idx] = vs; op[idx] = vo;
    }
    // S5
    load_wT(ko1, 72, wA); load_wT(av1, 72, wB);
    __syncthreads();
    g16_2w<NT1,72,72,true,true>(src, wA, ko1b, hA, wB, av1b, hB);
    __syncthreads();
    // S6: wA=qo1, KEEP wB=av1
    load_wT(qo1, 72, wA);
    __syncthreads();
    g16_2w<NT1,72,72,false,false>(op, wA, qo1b, uqo, wB, av1b, uav);
    g16_2w<NT1,8,8,false,false>(dl, wA + 64*65, nullptr, vqo, wB + 64*65, nullptr, vav);
    __syncthreads();
    for (int idx = tid; idx < 1024; idx += NT1) {
        hC[idx] = leaky(uav[idx]);
        g_u_av[b*1024 + idx] = uav[idx];
        g_v_av[b*1024 + idx] = vav[idx];
    }
    // S7
    load_wT(ko2, 64, wA); load_wT(av2w, 64, wB);
    __syncthreads();
    g16_2io<NT1,64,false,false>(hA, wA, ko2b, keyo, hB, wB, av2b, atts);
    __syncthreads();
    // S8: wA=qo2, KEEP wB=av2w
    for (int idx = tid; idx < 4096; idx += NT1) {
        int c = idx >> 6, t = idx & 63;
        wA[c*65 + t] = qo2[idx];
    }
    __syncthreads();
    g16_2io<NT1,64,false,false>(keyo, wA, nullptr, kq, hC, wB, av2b, Ps);
    if (tid < 16) {
        float s = 0.f;
        for (int c = 0; c < 64; c++) {
            int cc = (c + 4*tid) & 63;
            s = fmaf(keyo[tid*64 + cc], qo2b[cc], s);
        }
        kb_s[tid] = s;
    }
    __syncthreads();
    // S9: U, FmP -> global
    for (int idx = tid; idx < 4096; idx += NT1) {
        int t = idx >> 6, c = idx & 63;
        wA[c*65 + t] = fv1[t*128 + c];
        wB[c*65 + t] = fv1[t*128 + 64 + c];
    }
    __syncthreads();
    g16_2io<NT1,64,false,false>(atts, wA, fv1b, g_U + b*1024, Ps, wB, nullptr, g_FmP + b*1024);
    // S10: wo softmax
    if (tid < 256) {
        int i = tid >> 4, j = tid & 15;
        float wv = w_sm[tid];
        float acc = kb_s[i];
        #pragma unroll
        for (int d = 0; d < 64; d++) {
            int dd = (d + 2*j) & 63;
            float h = leaky(fmaf(wv, vqo[j*64 + dd], uqo[j*64 + dd]));
            acc = fmaf(kq[i*64 + dd], h, acc);
        }
        float sc = fminf(fmaxf(acc * 0.125f, -5.f), 5.f);
        float t = expf(sc);
        float mx = t;
        #pragma unroll
        for (int m = 1; m < 16; m <<= 1) mx = fmaxf(mx, __shfl_xor_sync(0xffffffffu, mx, m));
        float e = expf(t - mx), s = e;
        #pragma unroll
        for (int m = 1; m < 16; m <<= 1) s += __shfl_xor_sync(0xffffffffu, s, m);
        g_wo[b*256 + tid] = e / s;
    }
}

// ================= L2: 2 blocks per batch (i-halves), one full wave =================
__global__ void __launch_bounds__(NT2, 2)
L2(const float* __restrict__ fv2, const float* __restrict__ fv2b,
   float* __restrict__ out_val, float4* __restrict__ out4)
{
    extern __shared__ float sm[];
    float* Ct_s  = sm;             // 4160
    float* L_s   = sm + 4160;      // 8192 (128 rows)
    float* G_s   = sm + 12352;     // 8320 (128 rows, ld 65)
    float* u_s   = sm + 20672;     // 1024
    float* v_s   = sm + 21696;     // 1024
    float* U_s   = sm + 22720;     // 1040
    float* Fp_s  = sm + 23760;     // 1040
    float* w_s   = sm + 24800;     // 128
    float* wo_s  = sm + 24928;     // 256
    float* fb_s  = sm + 25184;     // 64
    float* fv2_s = sm + 25248;     // 512
    float* b2v   = sm + 25760;     // 8
    // 25768 floats = 103072 B -> 2 blocks/SM

    int bx = blockIdx.x;
    int b  = bx >> 1, ih = bx & 1;
    int tid = threadIdx.x;

    for (int idx = tid; idx < 4160; idx += NT2) Ct_s[idx] = g_Ct[idx];
    for (int idx = tid; idx < 1024; idx += NT2) {
        u_s[idx] = g_u_av[b*1024 + idx];
        v_s[idx] = g_v_av[b*1024 + idx];
        int r = idx >> 6, c = idx & 63;
        U_s [r*65 + c] = g_U  [b*1024 + idx];
        Fp_s[r*65 + c] = g_FmP[b*1024 + idx];
    }
    if (tid < 128) w_s[tid] = g_w[b*256 + ih*128 + tid];
    wo_s[tid] = g_wo[b*256 + tid];
    if (tid < 64)  fb_s[tid] = g_fb[tid];
    for (int idx = tid; idx < 512; idx += NT2) fv2_s[idx] = fv2[idx];
    if (tid < 8)   b2v[tid] = fv2b[tid];
    __syncthreads();
    // L rows [ih*128, ih*128+128): L[r][t] = leaky(u[j] + w*v[j]), j = r & 15
    for (int idx = tid; idx < 8192; idx += NT2) {
        int r = idx >> 6, t = idx & 63;
        int j = r & 15;
        L_s[idx] = leaky(fmaf(w_s[r], v_s[j*64 + t], u_s[j*64 + t]));
    }
    __syncthreads();
    gemm32(L_s,        Ct_s, G_s,          65);
    gemm32(L_s + 2048, Ct_s, G_s + 32*65,  65);
    gemm32(L_s + 4096, Ct_s, G_s + 64*65,  65);
    gemm32(L_s + 6144, Ct_s, G_s + 96*65,  65);
    __syncthreads();
    // value head: 128 pairs, t-halves. p = tid>>1, q = tid&1
    int p = tid >> 1, q = tid & 1;
    int il = p >> 4, j = p & 15;           // il in [0,8)
    float wo_r[16];
    #pragma unroll
    for (int k = 0; k < 16; k++) wo_r[k] = wo_s[j*16 + k];
    float wjj = wo_r[j];
    float vout[8];
    #pragma unroll
    for (int o = 0; o < 8; o++) vout[o] = 0.f;
    #pragma unroll 4
    for (int tt = 0; tt < 32; tt++) {
        int t = q*32 + tt;
        float m = 0.f;
        #pragma unroll
        for (int k = 0; k < 16; k++) m = fmaf(wo_r[k], G_s[(il*16 + k)*65 + t], m);
        float gij = G_s[(il*16 + j)*65 + t];
        float fbt = fb_s[t];
        float h = U_s[j*65 + t] + 0.0625f * (m + fbt + wjj * (Fp_s[j*65 + t] - gij - fbt));
        float ht = leaky(h);
        #pragma unroll
        for (int o = 0; o < 8; o++) vout[o] = fmaf(fv2_s[o*64 + t], ht, vout[o]);
    }
    #pragma unroll
    for (int o = 0; o < 8; o++) vout[o] += __shfl_xor_sync(0xffffffffu, vout[o], 1);
    if (q == 0) {
        #pragma unroll
        for (int o = 0; o < 8; o++) vout[o] += b2v[o];
        int ig = ih*8 + il;
        float4* dst = reinterpret_cast<float4*>(out_val + (size_t)(b*256 + ig*16 + j)*8);
        dst[0] = make_float4(vout[0], vout[1], vout[2], vout[3]);
        dst[1] = make_float4(vout[4], vout[5], vout[6], vout[7]);
    }
    // weights_obsz half: 512 float4s per block
    {
        const float4* wo4 = reinterpret_cast<const float4*>(wo_s);
        #pragma unroll
        for (int k = 0; k < 2; k++) {
            int q4 = ih*512 + k*256 + tid;
            out4[b*1024 + q4] = wo4[q4 & 63];
        }
    }
}

// ---------------- launcher ----------------
extern "C" void kernel_launch(void* const* d_in, const int* in_sizes, int n_in,
                              void* d_out, int out_size)
{
    const float* obs  = (const float*)d_in[0];
    const float* pol  = (const float*)d_in[1];
    const float* act  = (const float*)d_in[2];
    const float* kw1  = (const float*)d_in[3];  const float* kw1b = (const float*)d_in[4];
    const float* kw2  = (const float*)d_in[5];  const float* kw2b = (const float*)d_in[6];
    const float* qw1  = (const float*)d_in[7];  const float* qw1b = (const float*)d_in[8];
    const float* qw2  = (const float*)d_in[9];  const float* qw2b = (const float*)d_in[10];
    const float* ko1  = (const float*)d_in[11]; const float* ko1b = (const float*)d_in[12];
    const float* ko2  = (const float*)d_in[13]; const float* ko2b = (const float*)d_in[14];
    const float* qo1  = (const float*)d_in[15]; const float* qo1b = (const float*)d_in[16];
    const float* qo2  = (const float*)d_in[17]; const float* qo2b = (const float*)d_in[18];
    const float* av1  = (const float*)d_in[19]; const float* av1b = (const float*)d_in[20];
    const float* av2  = (const float*)d_in[21]; const float* av2b = (const float*)d_in[22];
    const float* fv1  = (const float*)d_in[23]; const float* fv1b = (const float*)d_in[24];
    const float* fv2  = (const float*)d_in[25]; const float* fv2b = (const float*)d_in[26];

    float* out      = (float*)d_out;
    float* out_val  = out;
    float* out_wz   = out + 262144;
    float* out_obsz = out + 294912;

    const int SM1 = 25504 * 4;   // 102016
    const int SM2 = 25768 * 4;   // 103072

    cudaFuncSetAttribute(L1, cudaFuncAttributeMaxDynamicSharedMemorySize, SM1);
    cudaFuncSetAttribute(L2, cudaFuncAttributeMaxDynamicSharedMemorySize, SM2);

    L1<<<129, NT1, SM1>>>(obs, pol, act,
                          kw1, kw1b, kw2, kw2b, qw1, qw1b, qw2, qw2b,
                          ko1, ko1b, ko2, ko2b, qo1, qo1b, qo2, qo2b,
                          av1, av1b, av2, av2b, fv1, fv1b, out_wz);
    L2<<<256, NT2, SM2>>>(fv2, fv2b, out_val,
                          reinterpret_cast<float4*>(out_obsz));
}